// round 7
// baseline (speedup 1.0000x reference)
#include <cuda_runtime.h>
#include <cstdint>

typedef uint32_t u32;

// Problem constants
#define BB 2
#define SS 1024
#define HH 8
#define DD 64
#define RR 32
#define KW 128
#define CC (HH*DD)          // 512
#define ZLEN (4*KW+SS)      // 1536
#define TS 64               // s per CTA
#define NTHREADS 256

// SMEM layout
#define ZSTRIDE 200                         // words/row; 200 % 32 == 8 -> conflict-free LDS.64
#define Z_BYTES   (RR * ZSTRIDE * 4)        // 25600
#define QKSTRIDE 132
#define QK_BYTES  (DD * QKSTRIDE * 4)       // 33792
#define W_BYTES   (2 * 256 * 4)             // 2048 (zero-padded filters)
#define DYN_BYTES (Z_BYTES + QK_BYTES + W_BYTES)   // 61440

__device__ __forceinline__ u32 cvt_tf32(float x) {
    u32 r; asm("cvt.rna.tf32.f32 %0, %1;" : "=r"(r) : "f"(x)); return r;
}

__device__ __forceinline__ void mma_tf32(float* c,
                                         u32 a0, u32 a1, u32 a2, u32 a3,
                                         u32 b0, u32 b1) {
    asm volatile(
        "mma.sync.aligned.m16n8k8.row.col.f32.tf32.tf32.f32 "
        "{%0,%1,%2,%3}, {%4,%5,%6,%7}, {%8,%9}, {%0,%1,%2,%3};"
        : "+f"(c[0]), "+f"(c[1]), "+f"(c[2]), "+f"(c[3])
        : "r"(a0), "r"(a1), "r"(a2), "r"(a3), "r"(b0), "r"(b1));
}

__global__ __launch_bounds__(NTHREADS, 2)
void convspe_mma_kernel(const float* __restrict__ qg,
                        const float* __restrict__ kg,
                        const float* __restrict__ wq,
                        const float* __restrict__ wk,
                        const float* __restrict__ zg,
                        float* __restrict__ out)
{
    extern __shared__ char dyn[];
    u32*   Zs   = reinterpret_cast<u32*>(dyn);                        // [32][200] tf32, pair-interleaved
    float* QK   = reinterpret_cast<float*>(dyn + Z_BYTES);            // [64 d][132]: rows 0-63 q, 64-127 k
    float* wpad = reinterpret_cast<float*>(dyn + Z_BYTES + QK_BYTES); // [2][256], band at [64,192)

    const int tid  = threadIdx.x;
    const int w    = tid >> 5;
    const int lane = tid & 31;
    const int g    = lane >> 2;       // row group 0..7
    const int qi   = lane & 3;        // quad index 0..3

    const int stile = blockIdx.x;     // 0..15
    const int h     = blockIdx.y;     // 0..7
    const int b     = blockIdx.z;     // 0..1
    const int s0    = stile * TS;
    const int cbase = h * DD;

    // ---- zero-fill wpad once (out-of-band entries stay 0 forever) ----
    wpad[tid]       = 0.f;
    wpad[tid + 256] = 0.f;

    // ---- stage q/k transposed: QK[d][row], rows 0-63 q, 64-127 k ----
    for (int idx = tid; idx < TS * 16; idx += NTHREADS) {  // 4 iters
        int srow = idx >> 4;
        int c4   = idx & 15;
        int goff = (((b * SS + s0 + srow) * HH + h) * DD) + c4 * 4;
        float4 q4 = *reinterpret_cast<const float4*>(qg + goff);
        float4 k4 = *reinterpret_cast<const float4*>(kg + goff);
        float qa[4] = {q4.x, q4.y, q4.z, q4.w};
        float ka[4] = {k4.x, k4.y, k4.z, k4.w};
        #pragma unroll
        for (int j = 0; j < 4; j++) {
            QK[(c4 * 4 + j) * QKSTRIDE + srow]      = qa[j];
            QK[(c4 * 4 + j) * QKSTRIDE + 64 + srow] = ka[j];
        }
    }

    // ---- per-warp constants: warp owns one 16-row m-tile ----
    const int f  = w >> 2;            // 0: qhat (filter wk), 1: khat (filter wq)
    const int tl = w & 3;             // m-tile index within filter half
    const float* wp = wpad + f * 256;

    float acc[4][4];                  // [n-tile][frag]
    #pragma unroll
    for (int n = 0; n < 4; n++)
        #pragma unroll
        for (int i = 0; i < 4; i++) acc[n][i] = 0.f;

    // ---- software pipeline: prefetch z (pairs-to-be) + filters for d into regs ----
    float4 z0[3], z1[3];
    float  wv;
    const float* wsel = (tid < 128) ? wk : wq;
    const int    wlane = tid & 127;

    // prefetch d = 0
    {
        const int c = cbase;
        #pragma unroll
        for (int i = 0; i < 3; i++) {
            int idx = tid + i * NTHREADS;       // 0..767 = 32 rows x 24 chunks
            int row = idx / 24;
            int cc  = idx - row * 24;
            const float* p = zg + ((size_t)((b * RR + row) * CC + c)) * ZLEN
                           + KW + s0 + cc * 8;
            z0[i] = *reinterpret_cast<const float4*>(p);
            z1[i] = *reinterpret_cast<const float4*>(p + 4);
        }
        wv = wsel[c * KW + wlane];
    }

    for (int d = 0; d < DD; d++) {
        __syncthreads();   // previous iteration's Z/w consumers done

        // -- store prefetched z as tf32 pairs (col j, j+4) --
        #pragma unroll
        for (int i = 0; i < 3; i++) {
            int idx = tid + i * NTHREADS;
            int row = idx / 24;
            int cc  = idx - row * 24;
            u32* dst = Zs + row * ZSTRIDE + cc * 8;
            *reinterpret_cast<uint2*>(dst)     = make_uint2(cvt_tf32(z0[i].x), cvt_tf32(z1[i].x));
            *reinterpret_cast<uint2*>(dst + 2) = make_uint2(cvt_tf32(z0[i].y), cvt_tf32(z1[i].y));
            *reinterpret_cast<uint2*>(dst + 4) = make_uint2(cvt_tf32(z0[i].z), cvt_tf32(z1[i].z));
            *reinterpret_cast<uint2*>(dst + 6) = make_uint2(cvt_tf32(z0[i].w), cvt_tf32(z1[i].w));
        }
        // -- store prefetched filter value --
        wpad[64 + wlane + (tid >> 7) * 256] = wv;

        // -- prefetch d+1 (overlaps the MMA loop below) --
        if (d + 1 < DD) {
            const int c = cbase + d + 1;
            #pragma unroll
            for (int i = 0; i < 3; i++) {
                int idx = tid + i * NTHREADS;
                int row = idx / 24;
                int cc  = idx - row * 24;
                const float* p = zg + ((size_t)((b * RR + row) * CC + c)) * ZLEN
                               + KW + s0 + cc * 8;
                z0[i] = *reinterpret_cast<const float4*>(p);
                z1[i] = *reinterpret_cast<const float4*>(p + 4);
            }
            wv = wsel[c * KW + wlane];
        }

        __syncthreads();

        // -- per-d A-row scalars for this warp's two row groups --
        const float qv0 = QK[d * QKSTRIDE + f * 64 + tl * 16 + g];
        const float qv1 = QK[d * QKSTRIDE + f * 64 + tl * 16 + g + 8];

        // -- 18 active chunks for this m-tile --
        #pragma unroll
        for (int u = 0; u < 18; u++) {
            const int wi = 64 + 8 * u + qi - g;
            const u32 a0 = cvt_tf32(qv0 * wp[wi]);
            const u32 a2 = cvt_tf32(qv0 * wp[wi + 4]);
            const u32 a1 = cvt_tf32(qv1 * wp[wi - 8]);
            const u32 a3 = cvt_tf32(qv1 * wp[wi - 4]);
            const int kw_ = (2 * tl + u) * 8 + qi * 2;   // pair word offset
            #pragma unroll
            for (int n = 0; n < 4; n++) {
                uint2 bb = *reinterpret_cast<const uint2*>(
                    Zs + (n * 8 + g) * ZSTRIDE + kw_);
                mma_tf32(acc[n], a0, a1, a2, a3, bb.x, bb.y);
            }
        }
    }

    // ---- epilogue: write accumulators straight to gmem ----
    const int khat_off = BB * SS * HH * RR;
    const int srow = tl * 16 + g;
    float* ob  = out + (f ? khat_off : 0)
               + ((b * SS + s0 + srow) * HH + h) * RR;
    float* ob8 = ob + 8 * HH * RR;    // srow + 8
    #pragma unroll
    for (int n = 0; n < 4; n++) {
        int col = n * 8 + 2 * qi;
        *reinterpret_cast<float2*>(ob  + col) = make_float2(acc[n][0], acc[n][1]);
        *reinterpret_cast<float2*>(ob8 + col) = make_float2(acc[n][2], acc[n][3]);
    }
}

extern "C" void kernel_launch(void* const* d_in, const int* in_sizes, int n_in,
                              void* d_out, int out_size)
{
    const float* queries = (const float*)d_in[0];
    const float* keys    = (const float*)d_in[1];
    const float* wq      = (const float*)d_in[2];
    const float* wk      = (const float*)d_in[3];
    const float* z       = (const float*)d_in[4];
    float* out = (float*)d_out;

    cudaFuncSetAttribute(convspe_mma_kernel,
                         cudaFuncAttributeMaxDynamicSharedMemorySize, DYN_BYTES);

    dim3 grid(SS / TS, HH, BB);   // 16 x 8 x 2 = 256 CTAs
    dim3 block(NTHREADS);
    convspe_mma_kernel<<<grid, block, DYN_BYTES>>>(queries, keys, wq, wk, z, out);
}